// round 5
// baseline (speedup 1.0000x reference)
#include <cuda_runtime.h>
#include <cuda_bf16.h>
#include <math.h>

#define NB 64
#define NN 512
#define GRID 592
#define NWARPS (GRID * 8)
#define ROW_UNITS (NB * NN)            // 32768
#define COORD_BASE ROW_UNITS
#define SMALL_BASE (ROW_UNITS + NB)
#define TOTAL_UNITS (SMALL_BASE + NB)
#define LN2 0.6931471805599453

// Scratch (__device__ globals; zeroed at load; re-zeroed by the last block)
// g_pair[b]: [2]=dot [3]=na2 [4]=aSum(=nt2) [5]=ent(log2) [6]=con  (small batches only)
__device__ double g_pair[NB][8];
__device__ double g_tot[8];            // 0=edge(log2) 1=sim 2=mse 3=smooth
__device__ int    g_done;

// ---------------------------------------------------------------------------
// lean per-element: edge products + sim. a in {0,1}; vb = element valid.
// x = a ? 1-p : p ; edge elem = 0.05*log2(x) + 0.95*log2(y), y = 1-x
__device__ __forceinline__ void lean_e(float p, float a, float s, bool vb,
                                       float& Px, float& Py, float& sim) {
    float w  = fmaf(-2.0f, p, 1.0f);
    float x0 = fmaf(a, w, p);
    float x  = vb ? x0 : 1.0f;
    float y  = vb ? 1.0f - x0 : 1.0f;
    float d  = vb ? s - a : 0.0f;
    Px *= x;
    Py *= y;
    sim = fmaf(d, d, sim);
}

// ---------------------------------------------------------------------------
__global__ __launch_bounds__(256, 4) void fused_kernel(
        const float* __restrict__ pc,      const float* __restrict__ adjm,
        const float* __restrict__ ncounts, const float* __restrict__ rsim,
        const float* __restrict__ temp,    const float* __restrict__ resw,
        const float* __restrict__ pts,     const float* __restrict__ adj,
        const void*  mask_raw,             float* __restrict__ out) {
    const int tid  = threadIdx.x;
    const int lane = tid & 31;
    const int w    = tid >> 5;
    const unsigned full = 0xffffffffu;

    __shared__ int s_cnt[NB];

    // ---- all 64 mask counts, computed per block (warp w: batches 8w..8w+7).
    // 2 pipelined ballot rounds on the prefix mask; dtype auto-detect.
    {
        const unsigned char* mb = (const unsigned char*)mask_raw;
        unsigned char b0 = mb[0], b1 = mb[1];   // elem (0,0) is always true
        int mode = (b1 != 0) ? 0 : ((b0 != 0) ? 1 : 2);
        auto rd = [&](int idx) -> bool {
            if (mode == 0)      return mb[idx] != 0;
            else if (mode == 1) return ((const int*)mask_raw)[idx] != 0;
            else                return ((const float*)mask_raw)[idx] != 0.0f;
        };
        bool on1[8];
        #pragma unroll
        for (int q = 0; q < 8; ++q)
            on1[q] = rd((w * 8 + q) * NN + lane * 16 + 15);
        int kk[8];
        #pragma unroll
        for (int q = 0; q < 8; ++q)
            kk[q] = __popc(__ballot_sync(full, on1[q]));
        bool on2[8];
        #pragma unroll
        for (int q = 0; q < 8; ++q)
            on2[q] = (kk[q] < 32 && lane < 16)
                   ? rd((w * 8 + q) * NN + 16 * kk[q] + lane) : false;
        #pragma unroll
        for (int q = 0; q < 8; ++q) {
            unsigned bal = __ballot_sync(full, on2[q]);
            int c = (kk[q] == 32) ? NN : 16 * kk[q] + __popc(bal & 0xFFFFu);
            if (lane == 0) s_cnt[w * 8 + q] = c;
        }
    }
    __syncthreads();

    // ---- persistent warp loop over flat unit space ----
    double accE = 0.0, accS = 0.0, accM = 0.0, accSm = 0.0;
    const int gw = blockIdx.x * 8 + w;

    for (int u = gw; u < TOTAL_UNITS; u += NWARPS) {
        if (u < ROW_UNITS) {
            // --- one row of a big batch ---
            const int b = u >> 9, i = u & 511;
            const int cnt = s_cnt[b];
            if (cnt <= 50 || i >= cnt) continue;
            const size_t rb = (size_t)u * NN;
            const float4* pr = (const float4*)(adjm + rb);
            const float4* ar = (const float4*)(adj  + rb);
            const float4* sr = (const float4*)(rsim + rb);
            const int cnt4 = (cnt + 3) >> 2;
            float Px = 1.f, Py = 1.f, sim = 0.f;

            #define DOSLOT(P4,A4,S4,JB) do {                               \
                lean_e(P4.x, A4.x, S4.x, (JB)+0 < cnt, Px, Py, sim);       \
                lean_e(P4.y, A4.y, S4.y, (JB)+1 < cnt, Px, Py, sim);       \
                lean_e(P4.z, A4.z, S4.z, (JB)+2 < cnt, Px, Py, sim);       \
                lean_e(P4.w, A4.w, S4.w, (JB)+3 < cnt, Px, Py, sim); } while(0)

            {   // phase A: cols lane, lane+32
                const int c0 = lane, c1 = lane + 32;
                const bool v0 = c0 < cnt4, v1 = c1 < cnt4;
                float4 p0={},a0={},s0={}, p1={},a1={},s1={};
                if (v0) { p0=__ldg(pr+c0); a0=__ldg(ar+c0); s0=__ldg(sr+c0); }
                if (v1) { p1=__ldg(pr+c1); a1=__ldg(ar+c1); s1=__ldg(sr+c1); }
                if (v0) DOSLOT(p0,a0,s0,4*c0);
                if (v1) DOSLOT(p1,a1,s1,4*c1);
            }
            {   // phase B: cols lane+64, lane+96
                const int c2 = lane + 64, c3 = lane + 96;
                const bool v2 = c2 < cnt4, v3 = c3 < cnt4;
                if (v2 | v3) {
                    float4 p2={},a2={},s2={}, p3={},a3={},s3={};
                    if (v2) { p2=__ldg(pr+c2); a2=__ldg(ar+c2); s2=__ldg(sr+c2); }
                    if (v3) { p3=__ldg(pr+c3); a3=__ldg(ar+c3); s3=__ldg(sr+c3); }
                    if (v2) DOSLOT(p2,a2,s2,4*c2);
                    if (v3) DOSLOT(p3,a3,s3,4*c3);
                }
            }
            #undef DOSLOT
            // 2 MUFU per row-lane (<=16 elems, min 0.02^16 ~ 6e-28: no underflow)
            accE += (double)fmaf(0.05f, __log2f(Px), 0.95f * __log2f(Py));
            accS += (double)sim;
        } else if (u < SMALL_BASE) {
            // --- coords for one batch ---
            const int b = u - COORD_BASE;
            const int cnt = s_cnt[b];
            const float2* pc2  = (const float2*)pc;
            const float2* pts2 = (const float2*)pts;
            float mse = 0.f, smo = 0.f;
            for (int n = lane; n < cnt; n += 32) {
                float2 uu = __ldg(pc2  + b * NN + n);
                float2 vv = __ldg(pts2 + b * NN + n);
                float dx = uu.x - vv.x, dy = uu.y - vv.y;
                mse += dx * dx + dy * dy;
                float ax = fabsf(dx), ay = fabsf(dy);
                smo += (ax < 1.0f ? 0.5f * dx * dx : ax - 0.5f)
                     + (ay < 1.0f ? 0.5f * dy * dy : ay - 0.5f);
            }
            accM += (double)mse;
            accSm += (double)smo;
        } else {
            // --- full pass for one small batch (cnt<=50) ---
            const int b = u - SMALL_BASE;
            const int cnt = s_cnt[b];
            if (cnt > 50) continue;
            float sL=0,sM=0,sAt=0,sSim=0,sDot=0,sP2=0,sA=0,sPt=0,sCon=0;
            for (int i = 0; i < cnt; ++i) {
                const size_t rb = ((size_t)b * NN + i) * NN;
                for (int j = lane; j < cnt; j += 32) {
                    float p = __ldg(adjm + rb + j);
                    float a = __ldg(adj  + rb + j);
                    float s = __ldg(rsim + rb + j);
                    float L = __log2f(p), M = __log2f(1.0f - p);
                    float t = L - M;
                    sL += L; sM += M;
                    sAt = fmaf(a, t, sAt);
                    float ds = s - a;
                    sSim = fmaf(ds, ds, sSim);
                    sDot = fmaf(p, a, sDot);
                    sP2  = fmaf(p, p, sP2);
                    sA  += a;
                    sPt  = fmaf(p, t, sPt);
                    sCon += fabsf(p - 0.5f);
                }
            }
            accE += (double)fmaf(0.05f, sL, fmaf(0.95f, sM, 0.9f * sAt));
            accS += (double)sSim;
            // warp-reduce the 5 per-batch (ari) quantities, lane 0 atomics
            float v5[5] = {sDot, sP2, sA, sM + sPt, sCon};
            #pragma unroll
            for (int k = 0; k < 5; ++k)
                #pragma unroll
                for (int o = 16; o; o >>= 1)
                    v5[k] += __shfl_down_sync(full, v5[k], o);
            if (lane == 0) {
                atomicAdd(&g_pair[b][2], (double)v5[0]);
                atomicAdd(&g_pair[b][3], (double)v5[1]);
                atomicAdd(&g_pair[b][4], (double)v5[2]);
                atomicAdd(&g_pair[b][5], (double)v5[3]);
                atomicAdd(&g_pair[b][6], (double)v5[4]);
            }
        }
    }

    // ---- one block-reduce of the 4 global accumulators ----
    {
        __shared__ double sh[8][4];
        double v[4] = {accE, accS, accM, accSm};
        #pragma unroll
        for (int k = 0; k < 4; ++k) {
            #pragma unroll
            for (int o = 16; o; o >>= 1) v[k] += __shfl_down_sync(full, v[k], o);
            if (lane == 0) sh[w][k] = v[k];
        }
        __syncthreads();
        if (w == 0 && lane < 4) {
            double x = 0.0;
            #pragma unroll
            for (int ww = 0; ww < 8; ++ww) x += sh[ww][lane];
            atomicAdd(&g_tot[lane], x);
        }
    }

    // ---- completion counter: last block finalizes ----
    __shared__ int s_last;
    __threadfence();                 // every thread ordered (atomics above)
    __syncthreads();
    if (tid == 0) {
        int done = atomicAdd(&g_done, 1);
        s_last = (done == GRID - 1) ? 1 : 0;
    }
    __syncthreads();
    if (!s_last) return;
    __threadfence();

    // ---- finalize (thread t<NB handles batch t; counts already in smem) ----
    double c2 = 0.0, cntd = 0.0, cl = 0.0, ac = 0.0;
    if (tid < NB) {
        int ci = s_cnt[tid];
        cntd   = (double)ci;
        c2     = cntd * cntd;
        double dc  = (double)__ldg(ncounts + tid) - cntd;
        double adc = fabs(dc);
        cl = (adc <= 1.0) ? 0.5 * dc * dc : adc - 0.5;
        if (ci > 5 && ci <= 50) {
            double dot  = g_pair[tid][2];
            double na2  = g_pair[tid][3];
            double nt2  = g_pair[tid][4];
            double entn = g_pair[tid][5] * LN2;
            double con  = g_pair[tid][6];
            double na   = sqrt(na2), nt = sqrt(nt2);
            double cosv = dot / (fmax(na, 1e-8) * fmax(nt, 1e-8));
            double n2   = fmax(c2, 1.0);
            ac = (-cosv - 0.2 * (con / n2)) + 0.1 * (-entn / n2);
        }
    }
    {
        __shared__ double sh2[8][4];
        double v[4] = {c2, cntd, cl, ac};
        #pragma unroll
        for (int k = 0; k < 4; ++k) {
            #pragma unroll
            for (int o = 16; o; o >>= 1) v[k] += __shfl_down_sync(full, v[k], o);
            if (lane == 0) sh2[w][k] = v[k];
        }
        __syncthreads();
        if (tid == 0) {
            double t4[4];
            #pragma unroll
            for (int k = 0; k < 4; ++k) {
                double x = 0.0;
                #pragma unroll
                for (int ww = 0; ww < 8; ++ww) x += sh2[ww][k];
                t4[k] = x;
            }
            double cnt2       = fmax(t4[0], 1.0);
            double cnt_coord  = fmax(t4[1] * 2.0, 1.0);
            double edge_loss  = -(g_tot[0] * LN2) / cnt2;
            double sim_loss   = g_tot[1] / cnt2;
            double coord_loss = 0.7 * (g_tot[2] / cnt_coord)
                              + 0.3 * (g_tot[3] / cnt_coord);
            double count_loss = t4[2] / (double)NB;
            double temp_reg   = fabs((double)__ldg(temp) - 1.0);
            double res_reg    = fabs((double)__ldg(resw) - 0.5);
            double total = coord_loss + 2.0 * edge_loss + 0.1 * count_loss
                         + 0.3 * sim_loss + 0.01 * (temp_reg + res_reg) + t4[3];
            out[0] = (float)total;
        }
    }
    __syncthreads();

    // ---- reset scratch for the next graph replay ----
    for (int k = tid; k < NB * 8; k += 256)
        ((double*)g_pair)[k] = 0.0;
    if (tid < 8) g_tot[tid] = 0.0;
    if (tid == 0) g_done = 0;
}

// ---------------------------------------------------------------------------
extern "C" void kernel_launch(void* const* d_in, const int* in_sizes, int n_in,
                              void* d_out, int out_size) {
    const float* pc      = (const float*)d_in[0];
    const float* adjm    = (const float*)d_in[1];
    const float* ncounts = (const float*)d_in[2];
    const float* rsim    = (const float*)d_in[3];
    const float* temp    = (const float*)d_in[4];
    const float* resw    = (const float*)d_in[5];
    const float* pts     = (const float*)d_in[6];
    const float* adj     = (const float*)d_in[7];
    const void*  mask    = d_in[8];

    fused_kernel<<<GRID, 256>>>(pc, adjm, ncounts, rsim, temp, resw,
                                pts, adj, mask, (float*)d_out);
    (void)in_sizes; (void)n_in; (void)out_size;
}

// round 6
// speedup vs baseline: 1.7113x; 1.7113x over previous
#include <cuda_runtime.h>
#include <cuda_bf16.h>
#include <math.h>

#define NB 64
#define NN 512
#define XB 8                      // blocks per batch
#define GRID (XB * NB)            // 512
#define LN2 0.6931471805599453

// Scratch (__device__ globals; zeroed at load; re-zeroed by the last block)
// g_pair[b]: [2]=dot [3]=na2 [4]=aSum(=nt2) [5]=ent(log2) [6]=con (small batches)
__device__ double g_pair[NB][8];
__device__ double g_tot[8];       // 0=edge(log2) 1=sim 2=mse 3=smooth
__device__ int    g_cnt[NB];
__device__ int    g_done;

// ---------------------------------------------------------------------------
// lean per-element: edge products + sim. a in {0,1}; vb = element valid.
// x = a ? 1-p : p ; edge elem = 0.05*log2(x) + 0.95*log2(y), y = 1-x
__device__ __forceinline__ void lean_e(float p, float a, float s, bool vb,
                                       float& Px, float& Py, float& sim) {
    float w  = fmaf(-2.0f, p, 1.0f);
    float x0 = fmaf(a, w, p);
    float x  = vb ? x0 : 1.0f;
    float y  = vb ? 1.0f - x0 : 1.0f;
    float d  = vb ? s - a : 0.0f;
    Px *= x;
    Py *= y;
    sim = fmaf(d, d, sim);
}

// ---------------------------------------------------------------------------
__global__ __launch_bounds__(256, 4) void fused_kernel(
        const float* __restrict__ pc,      const float* __restrict__ adjm,
        const float* __restrict__ ncounts, const float* __restrict__ rsim,
        const float* __restrict__ temp,    const float* __restrict__ resw,
        const float* __restrict__ pts,     const float* __restrict__ adj,
        const void*  mask_raw,             float* __restrict__ out) {
    const int b    = blockIdx.y;
    const int x    = blockIdx.x;
    const int tid  = threadIdx.x;
    const int lane = tid & 31;
    const int w    = tid >> 5;
    const unsigned full = 0xffffffffu;

    // ---- own-batch mask count, redundantly per warp (no block barrier) ----
    int cnt;
    {
        const unsigned char* mb = (const unsigned char*)mask_raw;
        unsigned char c0 = mb[0], c1 = mb[1];   // elem (0,0) is always true
        int mode = (c1 != 0) ? 0 : ((c0 != 0) ? 1 : 2);
        auto rd = [&](int idx) -> bool {
            if (mode == 0)      return mb[idx] != 0;
            else if (mode == 1) return ((const int*)mask_raw)[idx] != 0;
            else                return ((const float*)mask_raw)[idx] != 0.0f;
        };
        bool on1 = rd(b * NN + lane * 16 + 15);
        unsigned bal1 = __ballot_sync(full, on1);
        int k = __popc(bal1);                    // full 16-chunks (prefix mask)
        if (k == 32) cnt = NN;
        else {
            bool on2 = (lane < 16) ? rd(b * NN + 16 * k + lane) : false;
            unsigned bal2 = __ballot_sync(full, on2);
            cnt = 16 * k + __popc(bal2 & 0xFFFFu);
        }
    }

    double accE = 0.0, accS = 0.0, accM = 0.0, accSm = 0.0;

    // ---- coords + g_cnt store (x==0 blocks only) ----
    if (x == 0) {
        if (tid == 0) g_cnt[b] = cnt;
        const float2* pc2  = (const float2*)pc;
        const float2* pts2 = (const float2*)pts;
        float mse = 0.f, smo = 0.f;
        for (int n = tid; n < cnt; n += 256) {
            float2 uu = __ldg(pc2  + b * NN + n);
            float2 vv = __ldg(pts2 + b * NN + n);
            float dx = uu.x - vv.x, dy = uu.y - vv.y;
            mse += dx * dx + dy * dy;
            float ax = fabsf(dx), ay = fabsf(dy);
            smo += (ax < 1.0f ? 0.5f * dx * dx : ax - 0.5f)
                 + (ay < 1.0f ? 0.5f * dy * dy : ay - 0.5f);
        }
        accM  = (double)mse;
        accSm = (double)smo;
    }

    if (cnt > 50) {
        // ---- LEAN big-batch path: warp owns 8 contiguous rows ----
        const int rowbase = x * 64 + w * 8;
        const int cnt4 = (cnt + 3) >> 2;
        #pragma unroll 1
        for (int k = 0; k < 8; ++k) {
            const int i = rowbase + k;
            if (i >= cnt) break;
            const size_t rb = ((size_t)b * NN + i) * NN;
            const float4* pr = (const float4*)(adjm + rb);
            const float4* ar = (const float4*)(adj  + rb);
            const float4* sr = (const float4*)(rsim + rb);
            float Px = 1.f, Py = 1.f, sim = 0.f;

            #define DOSLOT(P4,A4,S4,JB) do {                               \
                lean_e(P4.x, A4.x, S4.x, (JB)+0 < cnt, Px, Py, sim);       \
                lean_e(P4.y, A4.y, S4.y, (JB)+1 < cnt, Px, Py, sim);       \
                lean_e(P4.z, A4.z, S4.z, (JB)+2 < cnt, Px, Py, sim);       \
                lean_e(P4.w, A4.w, S4.w, (JB)+3 < cnt, Px, Py, sim); } while(0)
            {   // phase A: float4 cols lane, lane+32
                const int ca = lane, cb = lane + 32;
                const bool va = ca < cnt4, vb2 = cb < cnt4;
                float4 p0={},a0={},s0={}, p1={},a1={},s1={};
                if (va)  { p0=__ldg(pr+ca); a0=__ldg(ar+ca); s0=__ldg(sr+ca); }
                if (vb2) { p1=__ldg(pr+cb); a1=__ldg(ar+cb); s1=__ldg(sr+cb); }
                if (va)  DOSLOT(p0,a0,s0,4*ca);
                if (vb2) DOSLOT(p1,a1,s1,4*cb);
            }
            {   // phase B: float4 cols lane+64, lane+96
                const int cc = lane + 64, cd = lane + 96;
                const bool vc = cc < cnt4, vd = cd < cnt4;
                if (vc | vd) {
                    float4 p2={},a2={},s2={}, p3={},a3={},s3={};
                    if (vc) { p2=__ldg(pr+cc); a2=__ldg(ar+cc); s2=__ldg(sr+cc); }
                    if (vd) { p3=__ldg(pr+cd); a3=__ldg(ar+cd); s3=__ldg(sr+cd); }
                    if (vc) DOSLOT(p2,a2,s2,4*cc);
                    if (vd) DOSLOT(p3,a3,s3,4*cd);
                }
            }
            #undef DOSLOT
            // 2 MUFU per row (<=16 elems/lane; min 0.02^16 ~ 6e-28: normal)
            accE += (double)fmaf(0.05f, __log2f(Px), 0.95f * __log2f(Py));
            accS += (double)sim;
        }
    } else {
        // ---- FULL small-batch path: warp w handles row x + 8w ----
        const int r = x + 8 * w;
        if (r < cnt) {
            float sL=0,sM=0,sAt=0,sSim=0,sDot=0,sP2=0,sA=0,sPt=0,sCon=0;
            const size_t rb = ((size_t)b * NN + r) * NN;
            for (int j = lane; j < cnt; j += 32) {
                float p = __ldg(adjm + rb + j);
                float a = __ldg(adj  + rb + j);
                float s = __ldg(rsim + rb + j);
                float L = __log2f(p), M = __log2f(1.0f - p);
                float t = L - M;
                sL += L; sM += M;
                sAt = fmaf(a, t, sAt);
                float ds = s - a;
                sSim = fmaf(ds, ds, sSim);
                sDot = fmaf(p, a, sDot);
                sP2  = fmaf(p, p, sP2);
                sA  += a;
                sPt  = fmaf(p, t, sPt);
                sCon += fabsf(p - 0.5f);
            }
            accE += (double)fmaf(0.05f, sL, fmaf(0.95f, sM, 0.9f * sAt));
            accS += (double)sSim;
            float v5[5] = {sDot, sP2, sA, sM + sPt, sCon};
            #pragma unroll
            for (int k = 0; k < 5; ++k)
                #pragma unroll
                for (int o = 16; o; o >>= 1)
                    v5[k] += __shfl_down_sync(full, v5[k], o);
            if (lane == 0) {
                atomicAdd(&g_pair[b][2], (double)v5[0]);
                atomicAdd(&g_pair[b][3], (double)v5[1]);
                atomicAdd(&g_pair[b][4], (double)v5[2]);
                atomicAdd(&g_pair[b][5], (double)v5[3]);
                atomicAdd(&g_pair[b][6], (double)v5[4]);
            }
        }
    }

    // ---- single block-reduce of the 4 global accumulators ----
    {
        __shared__ double sh[8][4];
        double v[4] = {accE, accS, accM, accSm};
        #pragma unroll
        for (int k = 0; k < 4; ++k) {
            #pragma unroll
            for (int o = 16; o; o >>= 1) v[k] += __shfl_down_sync(full, v[k], o);
            if (lane == 0) sh[w][k] = v[k];
        }
        __syncthreads();
        if (w == 0 && lane < 4) {
            double xx = 0.0;
            #pragma unroll
            for (int ww = 0; ww < 8; ++ww) xx += sh[ww][lane];
            atomicAdd(&g_tot[lane], xx);
        }
    }

    // ---- completion counter: last block finalizes ----
    __shared__ int s_last;
    __threadfence();
    __syncthreads();
    if (tid == 0) {
        int done = atomicAdd(&g_done, 1);
        s_last = (done == GRID - 1) ? 1 : 0;
    }
    __syncthreads();
    if (!s_last) return;
    __threadfence();

    // ---- finalize (thread t<NB handles batch t) ----
    double c2 = 0.0, cntd = 0.0, cl = 0.0, ac = 0.0;
    if (tid < NB) {
        int ci = g_cnt[tid];
        cntd   = (double)ci;
        c2     = cntd * cntd;
        double dc  = (double)__ldg(ncounts + tid) - cntd;
        double adc = fabs(dc);
        cl = (adc <= 1.0) ? 0.5 * dc * dc : adc - 0.5;
        if (ci > 5 && ci <= 50) {
            double dot  = g_pair[tid][2];
            double na2  = g_pair[tid][3];
            double nt2  = g_pair[tid][4];
            double entn = g_pair[tid][5] * LN2;
            double con  = g_pair[tid][6];
            double na   = sqrt(na2), nt = sqrt(nt2);
            double cosv = dot / (fmax(na, 1e-8) * fmax(nt, 1e-8));
            double n2   = fmax(c2, 1.0);
            ac = (-cosv - 0.2 * (con / n2)) + 0.1 * (-entn / n2);
        }
    }
    {
        __shared__ double sh2[8][4];
        double v[4] = {c2, cntd, cl, ac};
        #pragma unroll
        for (int k = 0; k < 4; ++k) {
            #pragma unroll
            for (int o = 16; o; o >>= 1) v[k] += __shfl_down_sync(full, v[k], o);
            if (lane == 0) sh2[w][k] = v[k];
        }
        __syncthreads();
        if (tid == 0) {
            double t4[4];
            #pragma unroll
            for (int k = 0; k < 4; ++k) {
                double xx = 0.0;
                #pragma unroll
                for (int ww = 0; ww < 8; ++ww) xx += sh2[ww][k];
                t4[k] = xx;
            }
            double cnt2       = fmax(t4[0], 1.0);
            double cnt_coord  = fmax(t4[1] * 2.0, 1.0);
            double edge_loss  = -(g_tot[0] * LN2) / cnt2;
            double sim_loss   = g_tot[1] / cnt2;
            double coord_loss = 0.7 * (g_tot[2] / cnt_coord)
                              + 0.3 * (g_tot[3] / cnt_coord);
            double count_loss = t4[2] / (double)NB;
            double temp_reg   = fabs((double)__ldg(temp) - 1.0);
            double res_reg    = fabs((double)__ldg(resw) - 0.5);
            double total = coord_loss + 2.0 * edge_loss + 0.1 * count_loss
                         + 0.3 * sim_loss + 0.01 * (temp_reg + res_reg) + t4[3];
            out[0] = (float)total;
        }
    }
    __syncthreads();

    // ---- reset scratch for the next graph replay ----
    for (int k = tid; k < NB * 8; k += 256)
        ((double*)g_pair)[k] = 0.0;
    if (tid < 8) g_tot[tid] = 0.0;
    if (tid == 0) g_done = 0;
}

// ---------------------------------------------------------------------------
extern "C" void kernel_launch(void* const* d_in, const int* in_sizes, int n_in,
                              void* d_out, int out_size) {
    const float* pc      = (const float*)d_in[0];
    const float* adjm    = (const float*)d_in[1];
    const float* ncounts = (const float*)d_in[2];
    const float* rsim    = (const float*)d_in[3];
    const float* temp    = (const float*)d_in[4];
    const float* resw    = (const float*)d_in[5];
    const float* pts     = (const float*)d_in[6];
    const float* adj     = (const float*)d_in[7];
    const void*  mask    = d_in[8];

    fused_kernel<<<dim3(XB, NB), 256>>>(pc, adjm, ncounts, rsim, temp, resw,
                                        pts, adj, mask, (float*)d_out);
    (void)in_sizes; (void)n_in; (void)out_size;
}

// round 7
// speedup vs baseline: 1.7132x; 1.0011x over previous
#include <cuda_runtime.h>
#include <cuda_bf16.h>
#include <math.h>

#define NB 64
#define NN 512
#define GRID 592
#define NWARP (GRID * 8)            // 4736
#define LN2 0.6931471805599453

// Scratch (__device__ globals; zeroed at load; re-zeroed by the last block)
// g_pair[b]: [2]=dot [3]=na2 [4]=aSum(=nt2) [5]=ent(log2) [6]=con (small batches)
__device__ double g_pair[NB][8];
__device__ double g_tot[8];         // 0=edge(log2) 1=sim 2=mse 3=smooth
__device__ int    g_done;

// ---------------------------------------------------------------------------
// lean per-element: edge products + sim. a in {0,1}; vb = element valid.
// x = a ? 1-p : p ; edge elem = 0.05*log2(x) + 0.95*log2(y), y = 1-x
__device__ __forceinline__ void lean_e(float p, float a, float s, bool vb,
                                       float& Px, float& Py, float& sim) {
    float w  = fmaf(-2.0f, p, 1.0f);
    float x0 = fmaf(a, w, p);
    float x  = vb ? x0 : 1.0f;
    float y  = vb ? 1.0f - x0 : 1.0f;
    float d  = vb ? s - a : 0.0f;
    Px *= x;
    Py *= y;
    sim = fmaf(d, d, sim);
}

// ---------------------------------------------------------------------------
__global__ __launch_bounds__(256, 4) void fused_kernel(
        const float* __restrict__ pc,      const float* __restrict__ adjm,
        const float* __restrict__ ncounts, const float* __restrict__ rsim,
        const float* __restrict__ temp,    const float* __restrict__ resw,
        const float* __restrict__ pts,     const float* __restrict__ adj,
        const void*  mask_raw,             float* __restrict__ out) {
    const int tid  = threadIdx.x;
    const int lane = tid & 31;
    const int w    = tid >> 5;
    const unsigned full = 0xffffffffu;

    __shared__ int s_cnt[NB];
    __shared__ int s_pref[NB + 1];

    // ---- all 64 mask counts (warp w: batches 8w..8w+7), 2 ballot rounds ----
    {
        const unsigned char* mb = (const unsigned char*)mask_raw;
        unsigned char c0 = mb[0], c1 = mb[1];   // elem (0,0) is always true
        int mode = (c1 != 0) ? 0 : ((c0 != 0) ? 1 : 2);
        auto rd = [&](int idx) -> bool {
            if (mode == 0)      return mb[idx] != 0;
            else if (mode == 1) return ((const int*)mask_raw)[idx] != 0;
            else                return ((const float*)mask_raw)[idx] != 0.0f;
        };
        bool on1[8];
        #pragma unroll
        for (int q = 0; q < 8; ++q)
            on1[q] = rd((w * 8 + q) * NN + lane * 16 + 15);
        int kk[8];
        #pragma unroll
        for (int q = 0; q < 8; ++q)
            kk[q] = __popc(__ballot_sync(full, on1[q]));
        bool on2[8];
        #pragma unroll
        for (int q = 0; q < 8; ++q)
            on2[q] = (kk[q] < 32 && lane < 16)
                   ? rd((w * 8 + q) * NN + 16 * kk[q] + lane) : false;
        #pragma unroll
        for (int q = 0; q < 8; ++q) {
            unsigned bal = __ballot_sync(full, on2[q]);
            int c = (kk[q] == 32) ? NN : 16 * kk[q] + __popc(bal & 0xFFFFu);
            if (lane == 0) s_cnt[w * 8 + q] = c;
        }
    }
    __syncthreads();

    // ---- prefix sum over the 64 counts (warp 0) ----
    if (w == 0) {
        int v0 = s_cnt[lane], v1 = s_cnt[lane + 32];
        int a0 = v0;
        #pragma unroll
        for (int o = 1; o < 32; o <<= 1) {
            int t = __shfl_up_sync(full, a0, o);
            if (lane >= o) a0 += t;
        }
        int tot0 = __shfl_sync(full, a0, 31);
        int a1 = v1;
        #pragma unroll
        for (int o = 1; o < 32; o <<= 1) {
            int t = __shfl_up_sync(full, a1, o);
            if (lane >= o) a1 += t;
        }
        a1 += tot0;
        s_pref[lane + 1]  = a0;
        s_pref[lane + 33] = a1;
        if (lane == 0) s_pref[0] = 0;
    }
    __syncthreads();
    const int R = s_pref[NB];           // total valid rows (~10K)

    double accE = 0.0, accS = 0.0, accM = 0.0, accSm = 0.0;
    const int gw = blockIdx.x * 8 + w;

    for (int u = gw; u < R + NB; u += NWARP) {
        if (u < R) {
            // ---- map global row u -> (b, i) via binary search ----
            int lo = 0, hi = NB;
            #pragma unroll
            for (int it = 0; it < 6; ++it) {
                int mid = (lo + hi) >> 1;
                if (s_pref[mid] <= u) lo = mid; else hi = mid;
            }
            const int b   = lo;
            const int i   = u - s_pref[lo];
            const int cnt = s_cnt[b];
            const size_t rb = ((size_t)b * NN + i) * NN;

            if (cnt > 50) {
                // ---- LEAN row: only edge + sim survive for cnt>50 ----
                const float4* pr = (const float4*)(adjm + rb);
                const float4* ar = (const float4*)(adj  + rb);
                const float4* sr = (const float4*)(rsim + rb);
                const int cnt4 = (cnt + 3) >> 2;
                float Px = 1.f, Py = 1.f, sim = 0.f;
                #define DOSLOT(P4,A4,S4,JB) do {                             \
                    lean_e(P4.x, A4.x, S4.x, (JB)+0 < cnt, Px, Py, sim);     \
                    lean_e(P4.y, A4.y, S4.y, (JB)+1 < cnt, Px, Py, sim);     \
                    lean_e(P4.z, A4.z, S4.z, (JB)+2 < cnt, Px, Py, sim);     \
                    lean_e(P4.w, A4.w, S4.w, (JB)+3 < cnt, Px, Py, sim); } while(0)
                const int ca = lane,      cb = lane + 32;
                const int cc = lane + 64, cd = lane + 96;
                const bool va = ca < cnt4, vb2 = cb < cnt4;
                const bool vc = cc < cnt4, vd  = cd < cnt4;
                float4 p0={},a0={},s0={}, p1={},a1={},s1={};
                float4 p2={},a2={},s2={}, p3={},a3={},s3={};
                if (va)  { p0=__ldg(pr+ca); a0=__ldg(ar+ca); s0=__ldg(sr+ca); }
                if (vb2) { p1=__ldg(pr+cb); a1=__ldg(ar+cb); s1=__ldg(sr+cb); }
                if (vc)  { p2=__ldg(pr+cc); a2=__ldg(ar+cc); s2=__ldg(sr+cc); }
                if (vd)  { p3=__ldg(pr+cd); a3=__ldg(ar+cd); s3=__ldg(sr+cd); }
                if (va)  DOSLOT(p0,a0,s0,4*ca);
                if (vb2) DOSLOT(p1,a1,s1,4*cb);
                if (vc)  DOSLOT(p2,a2,s2,4*cc);
                if (vd)  DOSLOT(p3,a3,s3,4*cd);
                #undef DOSLOT
                // 2 MUFU per row (<=16 elems/lane; min 0.02^16 ~ 6e-28)
                accE += (double)fmaf(0.05f, __log2f(Px), 0.95f * __log2f(Py));
                accS += (double)sim;
            } else {
                // ---- FULL row (small batch) ----
                float sL=0,sM=0,sAt=0,sSim=0,sDot=0,sP2=0,sA=0,sPt=0,sCon=0;
                for (int j = lane; j < cnt; j += 32) {
                    float p = __ldg(adjm + rb + j);
                    float a = __ldg(adj  + rb + j);
                    float s = __ldg(rsim + rb + j);
                    float L = __log2f(p), M = __log2f(1.0f - p);
                    float t = L - M;
                    sL += L; sM += M;
                    sAt = fmaf(a, t, sAt);
                    float ds = s - a;
                    sSim = fmaf(ds, ds, sSim);
                    sDot = fmaf(p, a, sDot);
                    sP2  = fmaf(p, p, sP2);
                    sA  += a;
                    sPt  = fmaf(p, t, sPt);
                    sCon += fabsf(p - 0.5f);
                }
                accE += (double)fmaf(0.05f, sL, fmaf(0.95f, sM, 0.9f * sAt));
                accS += (double)sSim;
                float v5[5] = {sDot, sP2, sA, sM + sPt, sCon};
                #pragma unroll
                for (int k = 0; k < 5; ++k)
                    #pragma unroll
                    for (int o = 16; o; o >>= 1)
                        v5[k] += __shfl_down_sync(full, v5[k], o);
                if (lane == 0) {
                    atomicAdd(&g_pair[b][2], (double)v5[0]);
                    atomicAdd(&g_pair[b][3], (double)v5[1]);
                    atomicAdd(&g_pair[b][4], (double)v5[2]);
                    atomicAdd(&g_pair[b][5], (double)v5[3]);
                    atomicAdd(&g_pair[b][6], (double)v5[4]);
                }
            }
        } else {
            // ---- coord unit for batch b ----
            const int b   = u - R;
            const int cnt = s_cnt[b];
            const float2* pc2  = (const float2*)pc;
            const float2* pts2 = (const float2*)pts;
            float mse = 0.f, smo = 0.f;
            for (int n = lane; n < cnt; n += 32) {
                float2 uu = __ldg(pc2  + b * NN + n);
                float2 vv = __ldg(pts2 + b * NN + n);
                float dx = uu.x - vv.x, dy = uu.y - vv.y;
                mse += dx * dx + dy * dy;
                float ax = fabsf(dx), ay = fabsf(dy);
                smo += (ax < 1.0f ? 0.5f * dx * dx : ax - 0.5f)
                     + (ay < 1.0f ? 0.5f * dy * dy : ay - 0.5f);
            }
            accM  += (double)mse;
            accSm += (double)smo;
        }
    }

    // ---- single block-reduce of the 4 global accumulators ----
    {
        __shared__ double sh[8][4];
        double v[4] = {accE, accS, accM, accSm};
        #pragma unroll
        for (int k = 0; k < 4; ++k) {
            #pragma unroll
            for (int o = 16; o; o >>= 1) v[k] += __shfl_down_sync(full, v[k], o);
            if (lane == 0) sh[w][k] = v[k];
        }
        __syncthreads();
        if (w == 0 && lane < 4) {
            double xx = 0.0;
            #pragma unroll
            for (int ww = 0; ww < 8; ++ww) xx += sh[ww][lane];
            atomicAdd(&g_tot[lane], xx);
        }
    }

    // ---- completion counter: last block finalizes ----
    __shared__ int s_last;
    __threadfence();
    __syncthreads();
    if (tid == 0) {
        int done = atomicAdd(&g_done, 1);
        s_last = (done == GRID - 1) ? 1 : 0;
    }
    __syncthreads();
    if (!s_last) return;
    __threadfence();

    // ---- finalize (thread t<NB handles batch t; counts in this block's smem) ----
    double c2 = 0.0, cntd = 0.0, cl = 0.0, ac = 0.0;
    if (tid < NB) {
        int ci = s_cnt[tid];
        cntd   = (double)ci;
        c2     = cntd * cntd;
        double dc  = (double)__ldg(ncounts + tid) - cntd;
        double adc = fabs(dc);
        cl = (adc <= 1.0) ? 0.5 * dc * dc : adc - 0.5;
        if (ci > 5 && ci <= 50) {
            double dot  = g_pair[tid][2];
            double na2  = g_pair[tid][3];
            double nt2  = g_pair[tid][4];
            double entn = g_pair[tid][5] * LN2;
            double con  = g_pair[tid][6];
            double na   = sqrt(na2), nt = sqrt(nt2);
            double cosv = dot / (fmax(na, 1e-8) * fmax(nt, 1e-8));
            double n2   = fmax(c2, 1.0);
            ac = (-cosv - 0.2 * (con / n2)) + 0.1 * (-entn / n2);
        }
    }
    {
        __shared__ double sh2[8][4];
        double v[4] = {c2, cntd, cl, ac};
        #pragma unroll
        for (int k = 0; k < 4; ++k) {
            #pragma unroll
            for (int o = 16; o; o >>= 1) v[k] += __shfl_down_sync(full, v[k], o);
            if (lane == 0) sh2[w][k] = v[k];
        }
        __syncthreads();
        if (tid == 0) {
            double t4[4];
            #pragma unroll
            for (int k = 0; k < 4; ++k) {
                double xx = 0.0;
                #pragma unroll
                for (int ww = 0; ww < 8; ++ww) xx += sh2[ww][k];
                t4[k] = xx;
            }
            double cnt2       = fmax(t4[0], 1.0);
            double cnt_coord  = fmax(t4[1] * 2.0, 1.0);
            double edge_loss  = -(g_tot[0] * LN2) / cnt2;
            double sim_loss   = g_tot[1] / cnt2;
            double coord_loss = 0.7 * (g_tot[2] / cnt_coord)
                              + 0.3 * (g_tot[3] / cnt_coord);
            double count_loss = t4[2] / (double)NB;
            double temp_reg   = fabs((double)__ldg(temp) - 1.0);
            double res_reg    = fabs((double)__ldg(resw) - 0.5);
            double total = coord_loss + 2.0 * edge_loss + 0.1 * count_loss
                         + 0.3 * sim_loss + 0.01 * (temp_reg + res_reg) + t4[3];
            out[0] = (float)total;
        }
    }
    __syncthreads();

    // ---- reset scratch for the next graph replay ----
    for (int k = tid; k < NB * 8; k += 256)
        ((double*)g_pair)[k] = 0.0;
    if (tid < 8) g_tot[tid] = 0.0;
    if (tid == 0) g_done = 0;
}

// ---------------------------------------------------------------------------
extern "C" void kernel_launch(void* const* d_in, const int* in_sizes, int n_in,
                              void* d_out, int out_size) {
    const float* pc      = (const float*)d_in[0];
    const float* adjm    = (const float*)d_in[1];
    const float* ncounts = (const float*)d_in[2];
    const float* rsim    = (const float*)d_in[3];
    const float* temp    = (const float*)d_in[4];
    const float* resw    = (const float*)d_in[5];
    const float* pts     = (const float*)d_in[6];
    const float* adj     = (const float*)d_in[7];
    const void*  mask    = d_in[8];

    fused_kernel<<<GRID, 256>>>(pc, adjm, ncounts, rsim, temp, resw,
                                pts, adj, mask, (float*)d_out);
    (void)in_sizes; (void)n_in; (void)out_size;
}

// round 8
// speedup vs baseline: 2.0220x; 1.1803x over previous
#include <cuda_runtime.h>
#include <cuda_bf16.h>
#include <math.h>

#define NB 64
#define NN 512
#define GRID 296
#define NWARP (GRID * 8)            // 2368
#define LN2 0.6931471805599453

// Scratch (__device__ globals; zeroed at load; re-zeroed by the last block)
// g_pair[b]: [2]=dot [3]=na2 [4]=aSum(=nt2) [5]=ent(log2) [6]=con (small batches)
__device__ double g_pair[NB][8];
__device__ double g_tot[8];         // 0=edge(log2) 1=sim 2=mse 3=smooth
__device__ int    g_done;

// ---------------------------------------------------------------------------
// lean per-element: edge products + sim. a in {0,1}; vb = element valid.
// x = a ? 1-p : p ; edge elem = 0.05*log2(x) + 0.95*log2(y), y = 1-x
__device__ __forceinline__ void lean_e(float p, float a, float s, bool vb,
                                       float& Px, float& Py, float& sim) {
    float w  = fmaf(-2.0f, p, 1.0f);
    float x0 = fmaf(a, w, p);
    float x  = vb ? x0 : 1.0f;
    float y  = vb ? 1.0f - x0 : 1.0f;
    float d  = vb ? s - a : 0.0f;
    Px *= x;
    Py *= y;
    sim = fmaf(d, d, sim);
}

// ---------------------------------------------------------------------------
__global__ __launch_bounds__(256, 2) void fused_kernel(
        const float* __restrict__ pc,      const float* __restrict__ adjm,
        const float* __restrict__ ncounts, const float* __restrict__ rsim,
        const float* __restrict__ temp,    const float* __restrict__ resw,
        const float* __restrict__ pts,     const float* __restrict__ adj,
        const void*  mask_raw,             float* __restrict__ out) {
    const int tid  = threadIdx.x;
    const int lane = tid & 31;
    const int w    = tid >> 5;
    const unsigned full = 0xffffffffu;

    __shared__ int s_cnt[NB];
    __shared__ int s_pref[NB + 1];

    // ---- all 64 mask counts (warp w: batches 8w..8w+7), 2 ballot rounds ----
    {
        const unsigned char* mb = (const unsigned char*)mask_raw;
        unsigned char c0 = mb[0], c1 = mb[1];   // elem (0,0) is always true
        int mode = (c1 != 0) ? 0 : ((c0 != 0) ? 1 : 2);
        auto rd = [&](int idx) -> bool {
            if (mode == 0)      return mb[idx] != 0;
            else if (mode == 1) return ((const int*)mask_raw)[idx] != 0;
            else                return ((const float*)mask_raw)[idx] != 0.0f;
        };
        bool on1[8];
        #pragma unroll
        for (int q = 0; q < 8; ++q)
            on1[q] = rd((w * 8 + q) * NN + lane * 16 + 15);
        int kk[8];
        #pragma unroll
        for (int q = 0; q < 8; ++q)
            kk[q] = __popc(__ballot_sync(full, on1[q]));
        bool on2[8];
        #pragma unroll
        for (int q = 0; q < 8; ++q)
            on2[q] = (kk[q] < 32 && lane < 16)
                   ? rd((w * 8 + q) * NN + 16 * kk[q] + lane) : false;
        #pragma unroll
        for (int q = 0; q < 8; ++q) {
            unsigned bal = __ballot_sync(full, on2[q]);
            int c = (kk[q] == 32) ? NN : 16 * kk[q] + __popc(bal & 0xFFFFu);
            if (lane == 0) s_cnt[w * 8 + q] = c;
        }
    }
    __syncthreads();

    // ---- prefix sum over the 64 counts (warp 0) ----
    if (w == 0) {
        int v0 = s_cnt[lane], v1 = s_cnt[lane + 32];
        int a0 = v0;
        #pragma unroll
        for (int o = 1; o < 32; o <<= 1) {
            int t = __shfl_up_sync(full, a0, o);
            if (lane >= o) a0 += t;
        }
        int tot0 = __shfl_sync(full, a0, 31);
        int a1 = v1;
        #pragma unroll
        for (int o = 1; o < 32; o <<= 1) {
            int t = __shfl_up_sync(full, a1, o);
            if (lane >= o) a1 += t;
        }
        a1 += tot0;
        s_pref[lane + 1]  = a0;
        s_pref[lane + 33] = a1;
        if (lane == 0) s_pref[0] = 0;
    }
    __syncthreads();
    const int R = s_pref[NB];           // total valid rows (~10K)

    double accE = 0.0, accS = 0.0, accM = 0.0, accSm = 0.0;
    const int gw = blockIdx.x * 8 + w;

    for (int u = gw; u < R + NB; u += NWARP) {
        if (u < R) {
            // ---- map global row u -> (b, i) via binary search ----
            int lo = 0, hi = NB;
            #pragma unroll
            for (int it = 0; it < 6; ++it) {
                int mid = (lo + hi) >> 1;
                if (s_pref[mid] <= u) lo = mid; else hi = mid;
            }
            const int b   = lo;
            const int i   = u - s_pref[lo];
            const int cnt = s_cnt[b];
            const size_t rb = ((size_t)b * NN + i) * NN;

            if (cnt > 50) {
                // ---- LEAN row: only edge + sim survive for cnt>50 ----
                const float4* pr = (const float4*)(adjm + rb);
                const float4* ar = (const float4*)(adj  + rb);
                const float4* sr = (const float4*)(rsim + rb);
                const int cnt4 = (cnt + 3) >> 2;
                float Px = 1.f, Py = 1.f, sim = 0.f;
                #define DOSLOT(P4,A4,S4,JB) do {                             \
                    lean_e(P4.x, A4.x, S4.x, (JB)+0 < cnt, Px, Py, sim);     \
                    lean_e(P4.y, A4.y, S4.y, (JB)+1 < cnt, Px, Py, sim);     \
                    lean_e(P4.z, A4.z, S4.z, (JB)+2 < cnt, Px, Py, sim);     \
                    lean_e(P4.w, A4.w, S4.w, (JB)+3 < cnt, Px, Py, sim); } while(0)
                const int ca = lane,      cb = lane + 32;
                const int cc = lane + 64, cd = lane + 96;
                const bool va = ca < cnt4, vb2 = cb < cnt4;
                const bool vc = cc < cnt4, vd  = cd < cnt4;
                // all 12 loads batched up-front (needs high reg budget)
                float4 p0={},a0={},s0={}, p1={},a1={},s1={};
                float4 p2={},a2={},s2={}, p3={},a3={},s3={};
                if (va)  p0 = __ldg(pr + ca);
                if (vb2) p1 = __ldg(pr + cb);
                if (vc)  p2 = __ldg(pr + cc);
                if (vd)  p3 = __ldg(pr + cd);
                if (va)  a0 = __ldg(ar + ca);
                if (vb2) a1 = __ldg(ar + cb);
                if (vc)  a2 = __ldg(ar + cc);
                if (vd)  a3 = __ldg(ar + cd);
                if (va)  s0 = __ldg(sr + ca);
                if (vb2) s1 = __ldg(sr + cb);
                if (vc)  s2 = __ldg(sr + cc);
                if (vd)  s3 = __ldg(sr + cd);
                if (va)  DOSLOT(p0,a0,s0,4*ca);
                if (vb2) DOSLOT(p1,a1,s1,4*cb);
                if (vc)  DOSLOT(p2,a2,s2,4*cc);
                if (vd)  DOSLOT(p3,a3,s3,4*cd);
                #undef DOSLOT
                // 2 MUFU per row (<=16 elems/lane; min 0.02^16 ~ 6e-28)
                accE += (double)fmaf(0.05f, __log2f(Px), 0.95f * __log2f(Py));
                accS += (double)sim;
            } else {
                // ---- FULL row (small batch) ----
                float sL=0,sM=0,sAt=0,sSim=0,sDot=0,sP2=0,sA=0,sPt=0,sCon=0;
                for (int j = lane; j < cnt; j += 32) {
                    float p = __ldg(adjm + rb + j);
                    float a = __ldg(adj  + rb + j);
                    float s = __ldg(rsim + rb + j);
                    float L = __log2f(p), M = __log2f(1.0f - p);
                    float t = L - M;
                    sL += L; sM += M;
                    sAt = fmaf(a, t, sAt);
                    float ds = s - a;
                    sSim = fmaf(ds, ds, sSim);
                    sDot = fmaf(p, a, sDot);
                    sP2  = fmaf(p, p, sP2);
                    sA  += a;
                    sPt  = fmaf(p, t, sPt);
                    sCon += fabsf(p - 0.5f);
                }
                accE += (double)fmaf(0.05f, sL, fmaf(0.95f, sM, 0.9f * sAt));
                accS += (double)sSim;
                float v5[5] = {sDot, sP2, sA, sM + sPt, sCon};
                #pragma unroll
                for (int k = 0; k < 5; ++k)
                    #pragma unroll
                    for (int o = 16; o; o >>= 1)
                        v5[k] += __shfl_down_sync(full, v5[k], o);
                if (lane == 0) {
                    atomicAdd(&g_pair[b][2], (double)v5[0]);
                    atomicAdd(&g_pair[b][3], (double)v5[1]);
                    atomicAdd(&g_pair[b][4], (double)v5[2]);
                    atomicAdd(&g_pair[b][5], (double)v5[3]);
                    atomicAdd(&g_pair[b][6], (double)v5[4]);
                }
            }
        } else {
            // ---- coord unit for batch b ----
            const int b   = u - R;
            const int cnt = s_cnt[b];
            const float2* pc2  = (const float2*)pc;
            const float2* pts2 = (const float2*)pts;
            float mse = 0.f, smo = 0.f;
            for (int n = lane; n < cnt; n += 32) {
                float2 uu = __ldg(pc2  + b * NN + n);
                float2 vv = __ldg(pts2 + b * NN + n);
                float dx = uu.x - vv.x, dy = uu.y - vv.y;
                mse += dx * dx + dy * dy;
                float ax = fabsf(dx), ay = fabsf(dy);
                smo += (ax < 1.0f ? 0.5f * dx * dx : ax - 0.5f)
                     + (ay < 1.0f ? 0.5f * dy * dy : ay - 0.5f);
            }
            accM  += (double)mse;
            accSm += (double)smo;
        }
    }

    // ---- single block-reduce of the 4 global accumulators ----
    {
        __shared__ double sh[8][4];
        double v[4] = {accE, accS, accM, accSm};
        #pragma unroll
        for (int k = 0; k < 4; ++k) {
            #pragma unroll
            for (int o = 16; o; o >>= 1) v[k] += __shfl_down_sync(full, v[k], o);
            if (lane == 0) sh[w][k] = v[k];
        }
        __syncthreads();
        if (w == 0 && lane < 4) {
            double xx = 0.0;
            #pragma unroll
            for (int ww = 0; ww < 8; ++ww) xx += sh[ww][lane];
            atomicAdd(&g_tot[lane], xx);
        }
    }

    // ---- completion counter: last block finalizes ----
    __shared__ int s_last;
    __threadfence();
    __syncthreads();
    if (tid == 0) {
        int done = atomicAdd(&g_done, 1);
        s_last = (done == GRID - 1) ? 1 : 0;
    }
    __syncthreads();
    if (!s_last) return;
    __threadfence();

    // ---- finalize (thread t<NB handles batch t; counts in this block's smem) ----
    double c2 = 0.0, cntd = 0.0, cl = 0.0, ac = 0.0;
    if (tid < NB) {
        int ci = s_cnt[tid];
        cntd   = (double)ci;
        c2     = cntd * cntd;
        double dc  = (double)__ldg(ncounts + tid) - cntd;
        double adc = fabs(dc);
        cl = (adc <= 1.0) ? 0.5 * dc * dc : adc - 0.5;
        if (ci > 5 && ci <= 50) {
            double dot  = g_pair[tid][2];
            double na2  = g_pair[tid][3];
            double nt2  = g_pair[tid][4];
            double entn = g_pair[tid][5] * LN2;
            double con  = g_pair[tid][6];
            double na   = sqrt(na2), nt = sqrt(nt2);
            double cosv = dot / (fmax(na, 1e-8) * fmax(nt, 1e-8));
            double n2   = fmax(c2, 1.0);
            ac = (-cosv - 0.2 * (con / n2)) + 0.1 * (-entn / n2);
        }
    }
    {
        __shared__ double sh2[8][4];
        double v[4] = {c2, cntd, cl, ac};
        #pragma unroll
        for (int k = 0; k < 4; ++k) {
            #pragma unroll
            for (int o = 16; o; o >>= 1) v[k] += __shfl_down_sync(full, v[k], o);
            if (lane == 0) sh2[w][k] = v[k];
        }
        __syncthreads();
        if (tid == 0) {
            double t4[4];
            #pragma unroll
            for (int k = 0; k < 4; ++k) {
                double xx = 0.0;
                #pragma unroll
                for (int ww = 0; ww < 8; ++ww) xx += sh2[ww][k];
                t4[k] = xx;
            }
            double cnt2       = fmax(t4[0], 1.0);
            double cnt_coord  = fmax(t4[1] * 2.0, 1.0);
            double edge_loss  = -(g_tot[0] * LN2) / cnt2;
            double sim_loss   = g_tot[1] / cnt2;
            double coord_loss = 0.7 * (g_tot[2] / cnt_coord)
                              + 0.3 * (g_tot[3] / cnt_coord);
            double count_loss = t4[2] / (double)NB;
            double temp_reg   = fabs((double)__ldg(temp) - 1.0);
            double res_reg    = fabs((double)__ldg(resw) - 0.5);
            double total = coord_loss + 2.0 * edge_loss + 0.1 * count_loss
                         + 0.3 * sim_loss + 0.01 * (temp_reg + res_reg) + t4[3];
            out[0] = (float)total;
        }
    }
    __syncthreads();

    // ---- reset scratch for the next graph replay ----
    for (int k = tid; k < NB * 8; k += 256)
        ((double*)g_pair)[k] = 0.0;
    if (tid < 8) g_tot[tid] = 0.0;
    if (tid == 0) g_done = 0;
}

// ---------------------------------------------------------------------------
extern "C" void kernel_launch(void* const* d_in, const int* in_sizes, int n_in,
                              void* d_out, int out_size) {
    const float* pc      = (const float*)d_in[0];
    const float* adjm    = (const float*)d_in[1];
    const float* ncounts = (const float*)d_in[2];
    const float* rsim    = (const float*)d_in[3];
    const float* temp    = (const float*)d_in[4];
    const float* resw    = (const float*)d_in[5];
    const float* pts     = (const float*)d_in[6];
    const float* adj     = (const float*)d_in[7];
    const void*  mask    = d_in[8];

    fused_kernel<<<GRID, 256>>>(pc, adjm, ncounts, rsim, temp, resw,
                                pts, adj, mask, (float*)d_out);
    (void)in_sizes; (void)n_in; (void)out_size;
}